// round 16
// baseline (speedup 1.0000x reference)
#include <cuda_runtime.h>
#include <cstddef>

#define BB 32
#define TT 512
#define DD 512
#define MAXLEN 2048
#define ROWS_PER_WARP 8
#define WARPS_PER_BLOCK 8
#define ROWS_PER_BLOCK (ROWS_PER_WARP * WARPS_PER_BLOCK)   // 64

// Fused length regulator, prologue amortized over 64 rows/block.
// __launch_bounds__(256, 6): cap regs at 42 so 6 blocks/SM fit ->
// wave tail shrinks from 284/740 to 136/888 blocks.
__global__ void __launch_bounds__(256, 6)
fused_regulate_kernel(const float4* __restrict__ x,
                      const int2*   __restrict__ dur2,   // duration as int2
                      float* __restrict__ out_f, int tail) {
    __shared__ int s_csum[TT];
    __shared__ int s_w[WARPS_PER_BLOCK];

    const int b    = blockIdx.y;
    const int tid  = threadIdx.x;
    const int lane = tid & 31;
    const int wid  = tid >> 5;

    // ---- prologue: inclusive scan of duration[b, 0..511], 2 elems/thread ----
    const int2 dd = __ldg(&dur2[b * (TT / 2) + tid]);
    const int pair = dd.x + dd.y;

    int v = pair;
    #pragma unroll
    for (int o = 1; o < 32; o <<= 1) {
        int n = __shfl_up_sync(0xffffffffu, v, o);
        if (lane >= o) v += n;
    }
    if (lane == 31) s_w[wid] = v;
    __syncthreads();

    if (tid < WARPS_PER_BLOCK) {
        int w = s_w[tid];
        #pragma unroll
        for (int o = 1; o < WARPS_PER_BLOCK; o <<= 1) {
            int n = __shfl_up_sync(0x000000ffu, w, o);
            if (tid >= o) w += n;
        }
        s_w[tid] = w;
    }
    __syncthreads();

    const int base_excl = (wid ? s_w[wid - 1] : 0) + (v - pair);
    ((int2*)s_csum)[tid] = make_int2(base_excl + dd.x, base_excl + pair);
    const int ds = s_w[WARPS_PER_BLOCK - 1];
    __syncthreads();

    // mel_lengths tail (one thread per batch): max(dur_sum, 1) as float
    if (blockIdx.x == 0 && tid == 0)
        out_f[tail + b] = (float)(ds > 0 ? ds : 1);

    // ---- per-warp frame indices: lanes 0-7 search 8 frames in parallel ----
    const int t0 = blockIdx.x * ROWS_PER_BLOCK + wid * ROWS_PER_WARP;
    int idx = -1;
    if (lane < ROWS_PER_WARP) {
        const int t = t0 + lane;
        if (t < ds) {
            // searchsorted right: first j with csum[j] > t.
            // range-512 worst case needs 10 halving steps.
            int lo = 0, hi = TT;
            #pragma unroll
            for (int step = 0; step < 10; step++) {
                if (lo < hi) {
                    int mid = (lo + hi) >> 1;
                    if (s_csum[mid] > t) hi = mid; else lo = mid + 1;
                }
            }
            idx = lo < (TT - 1) ? lo : (TT - 1);
        }
    }

    // broadcast the 8 indices to all lanes
    int ia[ROWS_PER_WARP];
    #pragma unroll
    for (int r = 0; r < ROWS_PER_WARP; r++)
        ia[r] = __shfl_sync(0xffffffffu, idx, r);

    // ---- copy engine: 4 chunks of 2 rows, MLP=8 per chunk ----
    const size_t xbase = (size_t)b * TT * (DD / 4);
    const float4 z = make_float4(0.f, 0.f, 0.f, 0.f);
    float4* obase = (float4*)out_f + ((size_t)b * MAXLEN + t0) * (DD / 4) + lane;

    #pragma unroll
    for (int r = 0; r < ROWS_PER_WARP; r += 2) {
        const int i0 = ia[r], i1 = ia[r + 1];
        float4 v0[4], v1[4];

        if ((i0 | i1) >= 0) {
            // common case: both rows valid -> 8 independent 16B loads batched
            const float4* xr0 = x + xbase + (size_t)i0 * (DD / 4) + lane;
            const float4* xr1 = x + xbase + (size_t)i1 * (DD / 4) + lane;
            #pragma unroll
            for (int k = 0; k < 4; k++) v0[k] = __ldg(xr0 + 32 * k);
            #pragma unroll
            for (int k = 0; k < 4; k++) v1[k] = __ldg(xr1 + 32 * k);
        } else {
            // boundary / padding: load only valid rows, zero the rest
            if (i0 >= 0) {
                const float4* xr0 = x + xbase + (size_t)i0 * (DD / 4) + lane;
                #pragma unroll
                for (int k = 0; k < 4; k++) v0[k] = __ldg(xr0 + 32 * k);
            } else {
                #pragma unroll
                for (int k = 0; k < 4; k++) v0[k] = z;
            }
            if (i1 >= 0) {
                const float4* xr1 = x + xbase + (size_t)i1 * (DD / 4) + lane;
                #pragma unroll
                for (int k = 0; k < 4; k++) v1[k] = __ldg(xr1 + 32 * k);
            } else {
                #pragma unroll
                for (int k = 0; k < 4; k++) v1[k] = z;
            }
        }

        float4* o0 = obase + (size_t)r * (DD / 4);
        float4* o1 = o0 + (DD / 4);
        // streaming stores: keep x L2-resident so DRAM stays pure-write
        #pragma unroll
        for (int k = 0; k < 4; k++) __stcs(o0 + 32 * k, v0[k]);
        #pragma unroll
        for (int k = 0; k < 4; k++) __stcs(o1 + 32 * k, v1[k]);
    }
}

extern "C" void kernel_launch(void* const* d_in, const int* in_sizes, int n_in,
                              void* d_out, int out_size) {
    const float* x   = (const float*)d_in[0];   // [32,512,512] f32
    const int*   dur = (const int*)d_in[1];     // [32,512] i32
    float* out = (float*)d_out;                 // [32*2048*512 + 32] f32

    const int tail = out_size - BB;  // mel_lengths live at the end

    dim3 grid(MAXLEN / ROWS_PER_BLOCK, BB);
    fused_regulate_kernel<<<grid, 256>>>((const float4*)x, (const int2*)dur,
                                         out, tail);
}

// round 17
// speedup vs baseline: 1.0575x; 1.0575x over previous
#include <cuda_runtime.h>
#include <cstddef>

#define BB 32
#define TT 512
#define DD 512
#define MAXLEN 2048
#define ROWS_PER_WARP 4
#define WARPS_PER_BLOCK 8
#define ROWS_PER_BLOCK (ROWS_PER_WARP * WARPS_PER_BLOCK)   // 32

// Fused length regulator, 32 rows/block (midpoint of the 16/64 sweep):
// halves the per-block prologue count vs grid=4096 while keeping the
// last wave fine-grained vs grid=1024. No occupancy cap (R16 showed the
// reg squeeze costs more than the tail it saves).
__global__ void __launch_bounds__(256)
fused_regulate_kernel(const float4* __restrict__ x,
                      const int2*   __restrict__ dur2,   // duration as int2
                      float* __restrict__ out_f, int tail) {
    __shared__ int s_csum[TT];
    __shared__ int s_w[WARPS_PER_BLOCK];

    const int b    = blockIdx.y;
    const int tid  = threadIdx.x;
    const int lane = tid & 31;
    const int wid  = tid >> 5;

    // ---- prologue: inclusive scan of duration[b, 0..511], 2 elems/thread ----
    const int2 dd = __ldg(&dur2[b * (TT / 2) + tid]);
    const int pair = dd.x + dd.y;

    int v = pair;
    #pragma unroll
    for (int o = 1; o < 32; o <<= 1) {
        int n = __shfl_up_sync(0xffffffffu, v, o);
        if (lane >= o) v += n;
    }
    if (lane == 31) s_w[wid] = v;
    __syncthreads();

    if (tid < WARPS_PER_BLOCK) {
        int w = s_w[tid];
        #pragma unroll
        for (int o = 1; o < WARPS_PER_BLOCK; o <<= 1) {
            int n = __shfl_up_sync(0x000000ffu, w, o);
            if (tid >= o) w += n;
        }
        s_w[tid] = w;
    }
    __syncthreads();

    const int base_excl = (wid ? s_w[wid - 1] : 0) + (v - pair);
    ((int2*)s_csum)[tid] = make_int2(base_excl + dd.x, base_excl + pair);
    const int ds = s_w[WARPS_PER_BLOCK - 1];
    __syncthreads();

    // mel_lengths tail (one thread per batch): max(dur_sum, 1) as float
    if (blockIdx.x == 0 && tid == 0)
        out_f[tail + b] = (float)(ds > 0 ? ds : 1);

    // ---- per-warp frame indices: lanes 0-3 search 4 frames in parallel ----
    const int t0 = blockIdx.x * ROWS_PER_BLOCK + wid * ROWS_PER_WARP;
    int idx = -1;
    if (lane < ROWS_PER_WARP) {
        const int t = t0 + lane;
        if (t < ds) {
            // searchsorted right: first j with csum[j] > t.
            // range-512 worst case needs 10 halving steps.
            int lo = 0, hi = TT;
            #pragma unroll
            for (int step = 0; step < 10; step++) {
                if (lo < hi) {
                    int mid = (lo + hi) >> 1;
                    if (s_csum[mid] > t) hi = mid; else lo = mid + 1;
                }
            }
            idx = lo < (TT - 1) ? lo : (TT - 1);
        }
    }

    // broadcast the 4 indices to all lanes
    int ia[ROWS_PER_WARP];
    #pragma unroll
    for (int r = 0; r < ROWS_PER_WARP; r++)
        ia[r] = __shfl_sync(0xffffffffu, idx, r);

    // ---- copy engine: 2 chunks of 2 rows, MLP=8 per chunk ----
    const size_t xbase = (size_t)b * TT * (DD / 4);
    const float4 z = make_float4(0.f, 0.f, 0.f, 0.f);
    float4* obase = (float4*)out_f + ((size_t)b * MAXLEN + t0) * (DD / 4) + lane;

    #pragma unroll
    for (int r = 0; r < ROWS_PER_WARP; r += 2) {
        const int i0 = ia[r], i1 = ia[r + 1];
        float4 v0[4], v1[4];

        if ((i0 | i1) >= 0) {
            // common case: both rows valid -> 8 independent 16B loads batched
            const float4* xr0 = x + xbase + (size_t)i0 * (DD / 4) + lane;
            const float4* xr1 = x + xbase + (size_t)i1 * (DD / 4) + lane;
            #pragma unroll
            for (int k = 0; k < 4; k++) v0[k] = __ldg(xr0 + 32 * k);
            #pragma unroll
            for (int k = 0; k < 4; k++) v1[k] = __ldg(xr1 + 32 * k);
        } else {
            // boundary / padding: load only valid rows, zero the rest
            if (i0 >= 0) {
                const float4* xr0 = x + xbase + (size_t)i0 * (DD / 4) + lane;
                #pragma unroll
                for (int k = 0; k < 4; k++) v0[k] = __ldg(xr0 + 32 * k);
            } else {
                #pragma unroll
                for (int k = 0; k < 4; k++) v0[k] = z;
            }
            if (i1 >= 0) {
                const float4* xr1 = x + xbase + (size_t)i1 * (DD / 4) + lane;
                #pragma unroll
                for (int k = 0; k < 4; k++) v1[k] = __ldg(xr1 + 32 * k);
            } else {
                #pragma unroll
                for (int k = 0; k < 4; k++) v1[k] = z;
            }
        }

        float4* o0 = obase + (size_t)r * (DD / 4);
        float4* o1 = o0 + (DD / 4);
        // streaming stores: keep x L2-resident so DRAM stays pure-write
        #pragma unroll
        for (int k = 0; k < 4; k++) __stcs(o0 + 32 * k, v0[k]);
        #pragma unroll
        for (int k = 0; k < 4; k++) __stcs(o1 + 32 * k, v1[k]);
    }
}

extern "C" void kernel_launch(void* const* d_in, const int* in_sizes, int n_in,
                              void* d_out, int out_size) {
    const float* x   = (const float*)d_in[0];   // [32,512,512] f32
    const int*   dur = (const int*)d_in[1];     // [32,512] i32
    float* out = (float*)d_out;                 // [32*2048*512 + 32] f32

    const int tail = out_size - BB;  // mel_lengths live at the end

    dim3 grid(MAXLEN / ROWS_PER_BLOCK, BB);
    fused_regulate_kernel<<<grid, 256>>>((const float4*)x, (const int2*)dur,
                                         out, tail);
}